// round 5
// baseline (speedup 1.0000x reference)
#include <cuda_runtime.h>
#include <math.h>

// AFM layer: B=2048, F=50, E=64, A=10, P=1225.
// out[b] = sum_p softmax(l)_p * q_p
//   l_p = sum_f h_f * relu( (x_i ∘ x_j)·W_f + b_f ),  q_p = (x_i ∘ x_j)·p
// One block per batch element; 256 threads. Two pair-passes (3+2 pairs/thread)
// to cut register peak -> 3 blocks/SM. f32x2 packed FMA, LDS.128 everywhere,
// q folded into weight col 10, pair LUT precomputed by init kernel.

#define NF 50
#define NE 64
#define NA 10
#define WC 12               // cols: 0-9 = W, 10 = p, 11 = 0
#define NPAIR 1225
#define NSLOT 1280
#define THREADS 256
#define XPITCH 68           // 16B-aligned rows; conflict-free LDS.128

typedef unsigned long long u64;

__device__ unsigned int g_pairoff[NSLOT];   // (i*XPITCH)<<16 | (j*XPITCH)

__global__ void init_pairs_kernel() {
    int p = blockIdx.x * blockDim.x + threadIdx.x;
    if (p >= NSLOT) return;
    unsigned int v;
    if (p < NPAIR) {
        float fp = (float)p;
        int i = (int)((2.0f * NF - 1.0f -
                       sqrtf((2.0f * NF - 1.0f) * (2.0f * NF - 1.0f) - 8.0f * fp)) * 0.5f);
        if (i < 0) i = 0;
        if (i > NF - 2) i = NF - 2;
        while (i + 1 <= NF - 2 && (i + 1) * (2 * NF - 1 - (i + 1)) / 2 <= p) ++i;
        while (i > 0 && i * (2 * NF - 1 - i) / 2 > p) --i;
        int j = p - i * (2 * NF - 1 - i) / 2 + i + 1;
        v = ((unsigned)(i * XPITCH) << 16) | (unsigned)(j * XPITCH);
    } else {
        v = (unsigned)XPITCH;   // dummy: i-off 0, j-off XPITCH (safe reads)
    }
    g_pairoff[p] = v;
}

__device__ __forceinline__ u64 f2_mul(u64 a, u64 b) {
    u64 d; asm("mul.rn.f32x2 %0, %1, %2;" : "=l"(d) : "l"(a), "l"(b)); return d;
}
__device__ __forceinline__ u64 f2_fma(u64 a, u64 b, u64 c) {
    u64 d; asm("fma.rn.f32x2 %0, %1, %2, %3;" : "=l"(d) : "l"(a), "l"(b), "l"(c)); return d;
}
__device__ __forceinline__ u64 f2_pack(float lo, float hi) {
    u64 d; asm("mov.b64 %0, {%1, %2};" : "=l"(d) : "f"(lo), "f"(hi)); return d;
}
__device__ __forceinline__ void f2_unpack(u64 v, float& lo, float& hi) {
    asm("mov.b64 {%0, %1}, %2;" : "=f"(lo), "=f"(hi) : "l"(v));
}

template<int NP>
__device__ __forceinline__ void run_pass(
    const float* __restrict__ xs, const float* __restrict__ Ws,
    const float* __restrict__ bs, const float* __restrict__ hs,
    int slot0, int tid, float* logit, float* qv)
{
    int xio[NP], xjo[NP];
#pragma unroll
    for (int t = 0; t < NP; ++t) {
        unsigned v = g_pairoff[slot0 + tid + t * THREADS];
        xio[t] = (int)(v >> 16);
        xjo[t] = (int)(v & 0xFFFFu);
    }

    u64 acc[NP][WC / 2];
#pragma unroll
    for (int t = 0; t < NP; ++t)
#pragma unroll
        for (int k = 0; k < WC / 2; ++k) acc[t][k] = 0ull;

#pragma unroll 1
    for (int ec = 0; ec < NE; ec += 4) {
        float pr[NP][4];
#pragma unroll
        for (int t = 0; t < NP; ++t) {
            ulonglong2 xi = *reinterpret_cast<const ulonglong2*>(xs + xio[t] + ec);
            ulonglong2 xj = *reinterpret_cast<const ulonglong2*>(xs + xjo[t] + ec);
            u64 a = f2_mul(xi.x, xj.x);
            u64 c = f2_mul(xi.y, xj.y);
            f2_unpack(a, pr[t][0], pr[t][1]);
            f2_unpack(c, pr[t][2], pr[t][3]);
        }
#pragma unroll
        for (int half = 0; half < 2; ++half) {
            // 2 e-rows of weights -> 6 LDS.128 (broadcast)
            u64 w0[WC / 2], w1[WC / 2];
            {
                const ulonglong2* r0 =
                    reinterpret_cast<const ulonglong2*>(Ws + (ec + 2 * half) * WC);
                ulonglong2 a = r0[0], b = r0[1], c = r0[2];
                w0[0] = a.x; w0[1] = a.y; w0[2] = b.x;
                w0[3] = b.y; w0[4] = c.x; w0[5] = c.y;
            }
            {
                const ulonglong2* r1 =
                    reinterpret_cast<const ulonglong2*>(Ws + (ec + 2 * half + 1) * WC);
                ulonglong2 a = r1[0], b = r1[1], c = r1[2];
                w1[0] = a.x; w1[1] = a.y; w1[2] = b.x;
                w1[3] = b.y; w1[4] = c.x; w1[5] = c.y;
            }
#pragma unroll
            for (int t = 0; t < NP; ++t) {
                u64 brA = f2_pack(pr[t][2 * half], pr[t][2 * half]);
                u64 brB = f2_pack(pr[t][2 * half + 1], pr[t][2 * half + 1]);
#pragma unroll
                for (int k = 0; k < WC / 2; ++k) acc[t][k] = f2_fma(brA, w0[k], acc[t][k]);
#pragma unroll
                for (int k = 0; k < WC / 2; ++k) acc[t][k] = f2_fma(brB, w1[k], acc[t][k]);
            }
        }
    }

    // logits + q
#pragma unroll
    for (int t = 0; t < NP; ++t) {
        float l = 0.0f;
#pragma unroll
        for (int k = 0; k < NA / 2; ++k) {
            float a0, a1;
            f2_unpack(acc[t][k], a0, a1);
            a0 += bs[2 * k];
            a1 += bs[2 * k + 1];
            a0 = a0 > 0.0f ? a0 : 0.0f;
            a1 = a1 > 0.0f ? a1 : 0.0f;
            l = fmaf(hs[2 * k], a0, l);
            l = fmaf(hs[2 * k + 1], a1, l);
        }
        float q0, q1;
        f2_unpack(acc[t][5], q0, q1);
        logit[t] = l;
        qv[t] = q0;
    }
}

__global__ __launch_bounds__(THREADS, 3)
void afm_kernel(const float* __restrict__ x,
                const float* __restrict__ W,
                const float* __restrict__ bvec,
                const float* __restrict__ hvec,
                const float* __restrict__ pvec,
                float* __restrict__ out)
{
    __shared__ __align__(16) float xs[NF * XPITCH];
    __shared__ __align__(16) float Ws[NE * WC];
    __shared__ float bs[NA];
    __shared__ float hs[NA];
    __shared__ float red[8];
    __shared__ float red2[8];
    __shared__ float bcast;

    const int tid  = threadIdx.x;
    const int lane = tid & 31;
    const int wid  = tid >> 5;
    const int b    = blockIdx.x;

    const float* xb = x + (size_t)b * (NF * NE);
    for (int idx = tid; idx < NF * NE; idx += THREADS) {
        int r = idx >> 6;
        int c = idx & 63;
        xs[r * XPITCH + c] = xb[idx];
    }
    for (int idx = tid; idx < NE * WC; idx += THREADS) {
        int e = idx / WC;
        int c = idx - e * WC;
        float v;
        if (c < NA)        v = W[e * NA + c];
        else if (c == NA)  v = pvec[e];
        else               v = 0.0f;
        Ws[idx] = v;
    }
    if (tid < NA) { bs[tid] = bvec[tid]; hs[tid] = hvec[tid]; }
    __syncthreads();

    float logit[5], qv[5];
    run_pass<3>(xs, Ws, bs, hs, 0,   tid, logit,     qv);
    run_pass<2>(xs, Ws, bs, hs, 768, tid, logit + 3, qv + 3);

    // mask invalid tail slots (pass B only; pass A slots 0..767 all valid)
    if (768 + tid >= NPAIR)  logit[3] = -INFINITY;
    if (1024 + tid >= NPAIR) logit[4] = -INFINITY;

    // ---- softmax-weighted scalar reduction ----
    float m = logit[0];
#pragma unroll
    for (int t = 1; t < 5; ++t) m = fmaxf(m, logit[t]);
#pragma unroll
    for (int o = 16; o > 0; o >>= 1)
        m = fmaxf(m, __shfl_xor_sync(0xFFFFFFFFu, m, o));
    if (lane == 0) red[wid] = m;
    __syncthreads();
    if (tid == 0) {
        float mm = red[0];
#pragma unroll
        for (int w = 1; w < THREADS / 32; ++w) mm = fmaxf(mm, red[w]);
        bcast = mm;
    }
    __syncthreads();
    const float mAll = bcast;

    float s = 0.0f, sq = 0.0f;
#pragma unroll
    for (int t = 0; t < 5; ++t) {
        float e = expf(logit[t] - mAll);   // -inf -> 0 for invalid slots
        s += e;
        sq = fmaf(e, qv[t], sq);
    }
#pragma unroll
    for (int o = 16; o > 0; o >>= 1) {
        s  += __shfl_xor_sync(0xFFFFFFFFu, s, o);
        sq += __shfl_xor_sync(0xFFFFFFFFu, sq, o);
    }
    if (lane == 0) { red[wid] = s; red2[wid] = sq; }
    __syncthreads();
    if (tid == 0) {
        float ss = 0.0f, ssq = 0.0f;
#pragma unroll
        for (int w = 0; w < THREADS / 32; ++w) { ss += red[w]; ssq += red2[w]; }
        out[b] = ssq / ss;
    }
}

extern "C" void kernel_launch(void* const* d_in, const int* in_sizes, int n_in,
                              void* d_out, int out_size)
{
    const float* x = (const float*)d_in[0];   // [B, 50, 64]
    const float* W = (const float*)d_in[1];   // [64, 10]
    const float* b = (const float*)d_in[2];   // [10]
    const float* h = (const float*)d_in[3];   // [10, 1]
    const float* p = (const float*)d_in[4];   // [64, 1]
    float* out = (float*)d_out;               // [B, 1]

    int B = in_sizes[0] / (NF * NE);
    init_pairs_kernel<<<(NSLOT + THREADS - 1) / THREADS, THREADS>>>();
    afm_kernel<<<B, THREADS>>>(x, W, b, h, p, out);
}

// round 6
// speedup vs baseline: 1.1117x; 1.1117x over previous
#include <cuda_runtime.h>
#include <math.h>

// AFM layer: B=2048, F=50, E=64, A=10, P=1225.
// out[b] = sum_p softmax(l)_p * q_p,  q folded as weight col 10.
// One block per batch element; 352 threads; each thread owns a 2x2 (i,j)
// Gram tile (4 pairs) -> x LDS traffic 1 load/pair/4e instead of 2.
// x stored as even/odd row arrays (pitch 68) for aligned, conflict-free LDS.128.

#define NF 50
#define NE 64
#define NA 10
#define WC 12               // cols: 0-9 = W, 10 = p, 11 = 0
#define NPAIR 1225
#define NTILE 325           // #{(bi,bj): 0<=bi<=bj<25}
#define THREADS 352         // 11 warps; one tile per thread
#define EPITCH 68           // dwords; 68 mod 32 = 4 -> conflict-free LDS.128
#define ZROW 25             // zero row index in xeven/xodd

typedef unsigned long long u64;

// per tile-slot: mask(4) << 28 | (bi*EPITCH) << 14 | (bj*EPITCH)
__device__ unsigned int g_tile[THREADS];

__global__ void init_tiles_kernel() {
    int s = blockIdx.x * blockDim.x + threadIdx.x;
    if (s >= THREADS) return;
    unsigned v;
    if (s < NTILE) {
        int rem = s, bi = 0;
        while (rem >= 25 - bi) { rem -= 25 - bi; ++bi; }
        int bj = bi + rem;
        unsigned mask = (bi < bj) ? 0xFu : 0x2u;   // diag: only (2bi,2bj+1)
        v = (mask << 28) | ((unsigned)(bi * EPITCH) << 14) | (unsigned)(bj * EPITCH);
    } else {
        v = ((unsigned)(ZROW * EPITCH) << 14) | (unsigned)(ZROW * EPITCH); // mask 0
    }
    g_tile[s] = v;
}

__device__ __forceinline__ u64 f2_fma(u64 a, u64 b, u64 c) {
    u64 d; asm("fma.rn.f32x2 %0, %1, %2, %3;" : "=l"(d) : "l"(a), "l"(b), "l"(c)); return d;
}
__device__ __forceinline__ u64 f2_bcast(float v) {
    u64 d; asm("mov.b64 %0, {%1, %1};" : "=l"(d) : "f"(v)); return d;
}
__device__ __forceinline__ void f2_unpack(u64 v, float& lo, float& hi) {
    asm("mov.b64 {%0, %1}, %2;" : "=f"(lo), "=f"(hi) : "l"(v));
}

__global__ __launch_bounds__(THREADS, 2)
void afm_kernel(const float* __restrict__ x,
                const float* __restrict__ W,
                const float* __restrict__ bvec,
                const float* __restrict__ hvec,
                const float* __restrict__ pvec,
                float* __restrict__ out)
{
    __shared__ __align__(16) float xev[(ZROW + 1) * EPITCH];  // even rows 0,2,..,48 + zero row
    __shared__ __align__(16) float xod[(ZROW + 1) * EPITCH];  // odd rows 1,3,..,49 + zero row
    __shared__ __align__(16) float Ws[NE * WC];
    __shared__ float bs[NA];
    __shared__ float hs[NA];
    __shared__ float red[11];
    __shared__ float red2[11];
    __shared__ float bcast;

    const int tid  = threadIdx.x;
    const int lane = tid & 31;
    const int wid  = tid >> 5;
    const int b    = blockIdx.x;

    // ---- load x[b] split into even/odd row arrays ----
    const float* xb = x + (size_t)b * (NF * NE);
    for (int idx = tid; idx < NF * NE; idx += THREADS) {
        int r = idx >> 6;
        int c = idx & 63;
        float v = xb[idx];
        if (r & 1) xod[(r >> 1) * EPITCH + c] = v;
        else       xev[(r >> 1) * EPITCH + c] = v;
    }
    // zero rows (for dummy tiles)
    for (int c = tid; c < EPITCH; c += THREADS) {
        xev[ZROW * EPITCH + c] = 0.0f;
        xod[ZROW * EPITCH + c] = 0.0f;
    }
    // ---- padded weights: cols 0-9 = W, col 10 = p, col 11 = 0 ----
    for (int idx = tid; idx < NE * WC; idx += THREADS) {
        int e = idx / WC;
        int c = idx - e * WC;
        float v;
        if (c < NA)        v = W[e * NA + c];
        else if (c == NA)  v = pvec[e];
        else               v = 0.0f;
        Ws[idx] = v;
    }
    if (tid < NA) { bs[tid] = bvec[tid]; hs[tid] = hvec[tid]; }
    __syncthreads();

    // ---- my 2x2 tile ----
    const unsigned tv  = g_tile[tid];
    const int bio  = (int)((tv >> 14) & 0x3FFFu);
    const int bjo  = (int)(tv & 0x3FFFu);
    const int mask = (int)(tv >> 28);

    // pairs: 0=(ie,je) 1=(ie,jo) 2=(io,je) 3=(io,jo)
    u64 acc[4][WC / 2];
#pragma unroll
    for (int p = 0; p < 4; ++p)
#pragma unroll
        for (int k = 0; k < WC / 2; ++k) acc[p][k] = 0ull;

#pragma unroll 1
    for (int ec = 0; ec < NE; ec += 4) {
        ulonglong2 Xie = *reinterpret_cast<const ulonglong2*>(xev + bio + ec);
        ulonglong2 Xio = *reinterpret_cast<const ulonglong2*>(xod + bio + ec);
        ulonglong2 Xje = *reinterpret_cast<const ulonglong2*>(xev + bjo + ec);
        ulonglong2 Xjo = *reinterpret_cast<const ulonglong2*>(xod + bjo + ec);
        float ie[4], io[4], je[4], jo[4];
        f2_unpack(Xie.x, ie[0], ie[1]); f2_unpack(Xie.y, ie[2], ie[3]);
        f2_unpack(Xio.x, io[0], io[1]); f2_unpack(Xio.y, io[2], io[3]);
        f2_unpack(Xje.x, je[0], je[1]); f2_unpack(Xje.y, je[2], je[3]);
        f2_unpack(Xjo.x, jo[0], jo[1]); f2_unpack(Xjo.y, jo[2], jo[3]);

#pragma unroll
        for (int h = 0; h < 4; ++h) {
            // one e-row of weights: 3 LDS.128 broadcast
            const ulonglong2* wr =
                reinterpret_cast<const ulonglong2*>(Ws + (ec + h) * WC);
            ulonglong2 wa = wr[0], wb = wr[1], wc = wr[2];
            u64 w[WC / 2];
            w[0] = wa.x; w[1] = wa.y; w[2] = wb.x;
            w[3] = wb.y; w[4] = wc.x; w[5] = wc.y;

            u64 br0 = f2_bcast(ie[h] * je[h]);
            u64 br1 = f2_bcast(ie[h] * jo[h]);
            u64 br2 = f2_bcast(io[h] * je[h]);
            u64 br3 = f2_bcast(io[h] * jo[h]);
#pragma unroll
            for (int k = 0; k < WC / 2; ++k) acc[0][k] = f2_fma(br0, w[k], acc[0][k]);
#pragma unroll
            for (int k = 0; k < WC / 2; ++k) acc[1][k] = f2_fma(br1, w[k], acc[1][k]);
#pragma unroll
            for (int k = 0; k < WC / 2; ++k) acc[2][k] = f2_fma(br2, w[k], acc[2][k]);
#pragma unroll
            for (int k = 0; k < WC / 2; ++k) acc[3][k] = f2_fma(br3, w[k], acc[3][k]);
        }
    }

    // ---- logits + q ----
    float logit[4], qv[4];
#pragma unroll
    for (int p = 0; p < 4; ++p) {
        float l = 0.0f;
#pragma unroll
        for (int k = 0; k < NA / 2; ++k) {
            float a0, a1;
            f2_unpack(acc[p][k], a0, a1);
            a0 += bs[2 * k];
            a1 += bs[2 * k + 1];
            a0 = a0 > 0.0f ? a0 : 0.0f;
            a1 = a1 > 0.0f ? a1 : 0.0f;
            l = fmaf(hs[2 * k], a0, l);
            l = fmaf(hs[2 * k + 1], a1, l);
        }
        float q0, q1;
        f2_unpack(acc[p][5], q0, q1);
        qv[p] = q0;
        logit[p] = (mask >> p) & 1 ? l : -INFINITY;
    }

    // ---- softmax-weighted scalar reduction ----
    float m = fmaxf(fmaxf(logit[0], logit[1]), fmaxf(logit[2], logit[3]));
#pragma unroll
    for (int o = 16; o > 0; o >>= 1)
        m = fmaxf(m, __shfl_xor_sync(0xFFFFFFFFu, m, o));
    if (lane == 0) red[wid] = m;
    __syncthreads();
    if (tid == 0) {
        float mm = red[0];
#pragma unroll
        for (int w = 1; w < THREADS / 32; ++w) mm = fmaxf(mm, red[w]);
        bcast = mm;
    }
    __syncthreads();
    const float mAll = bcast;

    float s = 0.0f, sq = 0.0f;
#pragma unroll
    for (int p = 0; p < 4; ++p) {
        float e = expf(logit[p] - mAll);   // -inf -> 0
        s += e;
        sq = fmaf(e, qv[p], sq);
    }
#pragma unroll
    for (int o = 16; o > 0; o >>= 1) {
        s  += __shfl_xor_sync(0xFFFFFFFFu, s, o);
        sq += __shfl_xor_sync(0xFFFFFFFFu, sq, o);
    }
    if (lane == 0) { red[wid] = s; red2[wid] = sq; }
    __syncthreads();
    if (tid == 0) {
        float ss = 0.0f, ssq = 0.0f;
#pragma unroll
        for (int w = 0; w < THREADS / 32; ++w) { ss += red[w]; ssq += red2[w]; }
        out[b] = ssq / ss;
    }
}

extern "C" void kernel_launch(void* const* d_in, const int* in_sizes, int n_in,
                              void* d_out, int out_size)
{
    const float* x = (const float*)d_in[0];   // [B, 50, 64]
    const float* W = (const float*)d_in[1];   // [64, 10]
    const float* b = (const float*)d_in[2];   // [10]
    const float* h = (const float*)d_in[3];   // [10, 1]
    const float* p = (const float*)d_in[4];   // [64, 1]
    float* out = (float*)d_out;               // [B, 1]

    int B = in_sizes[0] / (NF * NE);
    init_tiles_kernel<<<1, THREADS>>>();
    afm_kernel<<<B, THREADS>>>(x, W, b, h, p, out);
}